// round 6
// baseline (speedup 1.0000x reference)
#include <cuda_runtime.h>
#include <cuda_bf16.h>

#define DIM 128
#define TEMP_INV (1.0f / 0.07f)
#define STAGES 6

__device__ __forceinline__ float dot4(float4 a, float4 b) {
    return a.x * b.x + a.y * b.y + a.z * b.z + a.w * b.w;
}

__global__ __launch_bounds__(256, 8)
void la_loss_kernel(const float* __restrict__ codes,
                    const float* __restrict__ bank,
                    const void* __restrict__ idx_bg,
                    const void* __restrict__ idx_cl,
                    float* __restrict__ out,
                    int K)
{
    // per-warp private ring buffers: 8 warps x 6 stages x 512B = 24KB
    __shared__ float4 buf[8][STAGES][32];
    __shared__ float s[8];
    __shared__ int s_is64;

    const int b    = blockIdx.x;
    const int tid  = threadIdx.x;
    const int wid  = tid >> 5;      // 0..7
    const int lane = tid & 31;

    // ---- inline index-dtype detection (no separate kernel launch) ----
    // Index values < 2^20. If little-endian int64, all odd 32-bit words are 0.
    // If int32, odd words are random indices; P(all 64 zero) ~ 0.
    if (wid == 0) {
        const unsigned int* w = (const unsigned int*)idx_bg;
        unsigned int a = w[2 * lane + 1] | w[2 * lane + 65];
        int all0 = __all_sync(0xffffffffu, a == 0);
        if (lane == 0) s_is64 = all0;
    }

    // ---- load this batch row's code vector and normalize (per-warp) ----
    float4 c4 = reinterpret_cast<const float4*>(codes + (size_t)b * DIM)[lane];
    float ss = dot4(c4, c4);
#pragma unroll
    for (int o = 16; o; o >>= 1) ss += __shfl_xor_sync(0xffffffffu, ss, o);
    const float rn = rsqrtf(ss);
    const float4 v4 = make_float4(c4.x * rn, c4.y * rn, c4.z * rn, c4.w * rn);

    __syncthreads();
    const bool is64 = (s_is64 != 0);

    // warps 0-3 -> background indices, warps 4-7 -> close indices
    const void* idx = (wid < 4) ? idx_bg : idx_cl;
    const int wsub = wid & 3;
    const size_t base = (size_t)b * (size_t)K;
    const int F = (K - wsub + 3) >> 2;   // rows (fills) this warp owns

    // fill row f into ring slot; empty commit past the end keeps group
    // accounting uniform (empty groups complete immediately).
    auto fill = [&](int f, int slot) {
        if (f < F) {
            int m = wsub + 4 * f;
            long long ii;
            if (is64) ii = reinterpret_cast<const long long*>(idx)[base + m];
            else      ii = (long long)reinterpret_cast<const int*>(idx)[base + m];
            const float4* src = reinterpret_cast<const float4*>(bank + (size_t)ii * DIM) + lane;
            unsigned sad = (unsigned)__cvta_generic_to_shared(&buf[wid][slot][lane]);
            asm volatile("cp.async.cg.shared.global [%0], [%1], 16;\n"
                         :: "r"(sad), "l"(src));
        }
        asm volatile("cp.async.commit_group;\n");
    };

    // prologue: fill all 6 stages (groups for f=0..5 pending)
#pragma unroll
    for (int f = 0; f < STAGES; f++) fill(f, f);

    float acc = 0.0f;
    int slot = 0;                        // cycles 0,2,4 (pairs never wrap)
    const int P = (F + 1) >> 1;          // pair iterations
    for (int p = 0; p < P; p++) {
        // oldest 2 of the 6 pending groups (rows 2p, 2p+1) are complete
        asm volatile("cp.async.wait_group %0;\n" :: "n"(STAGES - 2));
        float4 rA = buf[wid][slot][lane];
        float4 rB = buf[wid][slot + 1][lane];

        // refill both slots with rows 2p+6, 2p+7 (or empty groups)
        fill(2 * p + STAGES, slot);
        fill(2 * p + STAGES + 1, slot + 1);
        slot += 2; if (slot == STAGES) slot = 0;

        // paired reduction: fold B into upper half-warp, then shared butterfly
        float d0 = dot4(rA, v4);
        float d1 = dot4(rB, v4);
        float t0 = __shfl_xor_sync(0xffffffffu, d0, 16);
        float t1 = __shfl_xor_sync(0xffffffffu, d1, 16);
        float e = (lane < 16) ? (d0 + t0) : (d1 + t1);
#pragma unroll
        for (int o = 8; o; o >>= 1) e += __shfl_xor_sync(0xffffffffu, e, o);
        // lanes [0,16): sum(rowA);  lanes [16,32): sum(rowB)
        bool valid = (lane < 16) | (2 * p + 1 < F);
        if (valid) acc += __expf(e * TEMP_INV);
    }
    asm volatile("cp.async.wait_group 0;\n");   // drain before exit

    // combine the two half-warp accumulators (lane0 gets sumA+sumB)
    acc += __shfl_xor_sync(0xffffffffu, acc, 16);

    if (lane == 0) s[wid] = acc;
    __syncthreads();
    if (tid == 0) {
        float d1 = s[0] + s[1] + s[2] + s[3];
        float d2 = s[4] + s[5] + s[6] + s[7];
        out[b] = logf(d1) - logf(d2);
    }
}

extern "C" void kernel_launch(void* const* d_in, const int* in_sizes, int n_in,
                              void* d_out, int out_size) {
    const float* codes = (const float*)d_in[0];
    const float* bank  = (const float*)d_in[1];
    const void*  ibg   = d_in[2];
    const void*  icl   = d_in[3];
    float* out = (float*)d_out;

    const int B = out_size;                 // 1024
    const int K = in_sizes[2] / B;          // 200

    la_loss_kernel<<<B, 256>>>(codes, bank, ibg, icl, out, K);
}

// round 7
// speedup vs baseline: 1.1635x; 1.1635x over previous
#include <cuda_runtime.h>
#include <cuda_bf16.h>

#define DIM 128
#define TEMP_INV (1.0f / 0.07f)
#define STAGES 6

__device__ __forceinline__ float dot4(float4 a, float4 b) {
    return a.x * b.x + a.y * b.y + a.z * b.z + a.w * b.w;
}

__global__ __launch_bounds__(256, 8)
void la_loss_kernel(const float* __restrict__ codes,
                    const float* __restrict__ bank,
                    const void* __restrict__ idx_bg,
                    const void* __restrict__ idx_cl,
                    float* __restrict__ out,
                    int K)
{
    // per-warp private ring buffers: 8 warps x 6 stages x 512B = 24KB
    __shared__ float4 buf[8][STAGES][32];
    __shared__ float s[8];

    const int b    = blockIdx.x;
    const int tid  = threadIdx.x;
    const int wid  = tid >> 5;      // 0..7
    const int lane = tid & 31;

    // warps 0-3 -> background indices, warps 4-7 -> close indices
    const void* idx = (wid < 4) ? idx_bg : idx_cl;

    // ---- per-warp inline index-dtype detection (no extra launch, no sync) ----
    // Index values < 2^20. If little-endian int64, all odd 32-bit words are 0.
    // If int32, those words are random indices; P(32 all zero) ~ 0.
    const unsigned int* w = (const unsigned int*)idx;
    const bool is64 = __all_sync(0xffffffffu, w[2 * lane + 1] == 0u);

    // ---- load this batch row's code vector and normalize (per-warp) ----
    float4 c4 = reinterpret_cast<const float4*>(codes + (size_t)b * DIM)[lane];
    float ss = dot4(c4, c4);
#pragma unroll
    for (int o = 16; o; o >>= 1) ss += __shfl_xor_sync(0xffffffffu, ss, o);
    const float rn = rsqrtf(ss);
    const float4 v4 = make_float4(c4.x * rn, c4.y * rn, c4.z * rn, c4.w * rn);

    const int wsub = wid & 3;
    const size_t base = (size_t)b * (size_t)K;
    const int F = (K - wsub + 3) >> 2;   // rows (fills) this warp owns

    // fill row f into ring slot; empty commit past the end keeps group
    // accounting uniform (empty groups complete immediately).
    auto fill = [&](int f, int slot) {
        if (f < F) {
            int m = wsub + 4 * f;
            long long ii;
            if (is64) ii = reinterpret_cast<const long long*>(idx)[base + m];
            else      ii = (long long)reinterpret_cast<const int*>(idx)[base + m];
            const float4* src = reinterpret_cast<const float4*>(bank + (size_t)ii * DIM) + lane;
            unsigned sad = (unsigned)__cvta_generic_to_shared(&buf[wid][slot][lane]);
            asm volatile("cp.async.cg.shared.global [%0], [%1], 16;\n"
                         :: "r"(sad), "l"(src));
        }
        asm volatile("cp.async.commit_group;\n");
    };

    // prologue: fill all 6 stages (groups for f=0..5 pending)
#pragma unroll
    for (int f = 0; f < STAGES; f++) fill(f, f);

    float acc = 0.0f;
    int slot = 0;
    for (int t = 0; t < F; t++) {
        // oldest of the 6 pending groups (row t) is complete
        asm volatile("cp.async.wait_group %0;\n" :: "n"(STAGES - 1));
        float4 r = buf[wid][slot][lane];   // each lane reads the 16B it filled

        // refill this slot with row t+6 (or empty group past the end)
        fill(t + STAGES, slot);
        if (++slot == STAGES) slot = 0;

        float d = dot4(r, v4);
#pragma unroll
        for (int o = 16; o; o >>= 1) d += __shfl_xor_sync(0xffffffffu, d, o);
        acc += __expf(d * TEMP_INV);
    }
    asm volatile("cp.async.wait_group 0;\n");   // drain before exit

    if (lane == 0) s[wid] = acc;
    __syncthreads();
    if (tid == 0) {
        float d1 = s[0] + s[1] + s[2] + s[3];
        float d2 = s[4] + s[5] + s[6] + s[7];
        out[b] = logf(d1) - logf(d2);
    }
}

extern "C" void kernel_launch(void* const* d_in, const int* in_sizes, int n_in,
                              void* d_out, int out_size) {
    const float* codes = (const float*)d_in[0];
    const float* bank  = (const float*)d_in[1];
    const void*  ibg   = d_in[2];
    const void*  icl   = d_in[3];
    float* out = (float*)d_out;

    const int B = out_size;                 // 1024
    const int K = in_sizes[2] / B;          // 200

    la_loss_kernel<<<B, 256>>>(codes, bank, ibg, icl, out, K);
}